// round 1
// baseline (speedup 1.0000x reference)
#include <cuda_runtime.h>
#include <cstdint>

#define BB 16
#define NN 2048
#define MM 1024
#define TT 256

#define IOU_THR 0.5f
#define SCALE_C (4.5392368437151541e-04f)  // 1/sqrt(1920^2+1080^2)
#define A_TRK 2.0f
#define A_SPA 1.5f
#define A_TMP 1.8f
#define B_FP 0.9f
#define B_FN 0.9f
#define G_SW 1.5f

// ---------------- device scratch (no allocations allowed) ----------------
__device__ int   g_gt_cnt[BB][TT];
__device__ int   g_pr_cnt[BB][TT];
__device__ float g_meanw[BB][TT];
__device__ float g_meanh[BB][TT];
__device__ float g_fn[BB];
__device__ int   g_nuni[BB];
__device__ int   g_nvalid[BB];
__device__ float g_match[BB];
__device__ float g_fp[BB];
__device__ int   g_sw[BB];
__device__ float g_spatial[BB];
__device__ float g_temporal[BB];

// ======================= K1: histograms + fn + counts =======================
__global__ __launch_bounds__(256) void k1_hist(
    const float4* __restrict__ pboxes,   // [B][N] float4
    const int*    __restrict__ pid,      // [B][N]
    const int*    __restrict__ gid)      // [B][M]
{
    const int b = blockIdx.x;
    const int tid = threadIdx.x;
    __shared__ int   s_gt[TT];
    __shared__ int   s_pr[TT];
    __shared__ float s_sumw[TT];
    __shared__ float s_sumh[TT];

    s_gt[tid] = 0; s_pr[tid] = 0; s_sumw[tid] = 0.f; s_sumh[tid] = 0.f;
    if (tid == 0) { g_match[b] = 0.f; g_fp[b] = 0.f; g_sw[b] = 0; }
    __syncthreads();

    const int* gidb = gid + b * MM;
    for (int j = tid; j < MM; j += 256)
        atomicAdd(&s_gt[gidb[j]], 1);

    const int* pidb = pid + b * NN;
    const float4* pb = pboxes + b * NN;
    int nvalid = 0;
    for (int i = tid; i < NN; i += 256) {
        int p = pidb[i];
        if (p > 0) {
            float4 bx = pb[i];
            atomicAdd(&s_pr[p], 1);
            atomicAdd(&s_sumw[p], bx.z - bx.x);
            atomicAdd(&s_sumh[p], bx.w - bx.y);
            nvalid++;
        }
    }
    __syncthreads();

    const int t = tid;
    int cnt = s_pr[t];
    int gc  = s_gt[t];
    g_gt_cnt[b][t] = gc;
    g_pr_cnt[b][t] = cnt;
    float cs = fmaxf((float)cnt, 1.f);
    g_meanw[b][t] = s_sumw[t] / cs;
    g_meanh[b][t] = s_sumh[t] / cs;

    float fn = (gc > 0 && cnt == 0) ? (float)gc : 0.f;
    int   nu = (cnt > 0) ? 1 : 0;

    // block reduce fn(float), nu(int), nvalid(int)
    int lane = tid & 31, w = tid >> 5;
    #pragma unroll
    for (int o = 16; o > 0; o >>= 1) {
        fn     += __shfl_down_sync(0xffffffffu, fn, o);
        nu     += __shfl_down_sync(0xffffffffu, nu, o);
        nvalid += __shfl_down_sync(0xffffffffu, nvalid, o);
    }
    __shared__ float r_f[8];
    __shared__ int   r_u[8], r_v[8];
    if (lane == 0) { r_f[w] = fn; r_u[w] = nu; r_v[w] = nvalid; }
    __syncthreads();
    if (tid == 0) {
        float F = 0.f; int U = 0, V = 0;
        #pragma unroll
        for (int k = 0; k < 8; k++) { F += r_f[k]; U += r_u[k]; V += r_v[k]; }
        g_fn[b] = F; g_nuni[b] = U; g_nvalid[b] = V;
    }
}

// ======================= K2: spatial deviation + temporal =======================
__global__ __launch_bounds__(256) void k2_spat_temp(
    const float4* __restrict__ pboxes,
    const int*    __restrict__ pid)
{
    const int b = blockIdx.x;
    const int tid = threadIdx.x;
    __shared__ float s_mw[TT], s_mh[TT], s_sdw[TT], s_sdh[TT];
    __shared__ int   s_pc[TT];
    __shared__ int   s_pid[NN];
    __shared__ float s_cx[NN], s_cy[NN];

    s_mw[tid]  = g_meanw[b][tid];
    s_mh[tid]  = g_meanh[b][tid];
    s_pc[tid]  = g_pr_cnt[b][tid];
    s_sdw[tid] = 0.f; s_sdh[tid] = 0.f;
    __syncthreads();

    const int* pidb = pid + b * NN;
    const float4* pb = pboxes + b * NN;
    for (int i = tid; i < NN; i += 256) {
        int p = pidb[i];
        float4 bx = pb[i];
        s_pid[i] = p;
        s_cx[i] = (bx.x + bx.z) * 0.5f;
        s_cy[i] = (bx.y + bx.w) * 0.5f;
        if (p > 0) {
            atomicAdd(&s_sdw[p], fabsf((bx.z - bx.x) - s_mw[p]));
            atomicAdd(&s_sdh[p], fabsf((bx.w - bx.y) - s_mh[p]));
        }
    }
    __syncthreads();

    // spatial per-track
    const int t = tid;
    int cnt = s_pc[t];
    float sp = 0.f;
    if (cnt > 1) sp = (s_sdw[t] + s_sdh[t]) * SCALE_C / (float)cnt;

    // temporal per-track: scan preds in original order (== stable sort order)
    float tp = 0.f;
    if (t > 0 && cnt > 2) {
        float c0x = 0.f, c0y = 0.f, c1x = 0.f, c1y = 0.f;
        int   seen = 0;
        float sa = 0.f;
        for (int i = 0; i < NN; i++) {
            if (s_pid[i] == t) {
                float cx = s_cx[i], cy = s_cy[i];
                if (seen >= 2) {
                    float ax = (cx - 2.f * c1x + c0x) * SCALE_C;
                    float ay = (cy - 2.f * c1y + c0y) * SCALE_C;
                    sa += sqrtf(ax * ax + ay * ay);
                }
                c0x = c1x; c0y = c1y; c1x = cx; c1y = cy;
                seen++;
            }
        }
        tp = sa / (float)(cnt - 2);
    }

    // reduce sp, tp
    int lane = tid & 31, w = tid >> 5;
    #pragma unroll
    for (int o = 16; o > 0; o >>= 1) {
        sp += __shfl_down_sync(0xffffffffu, sp, o);
        tp += __shfl_down_sync(0xffffffffu, tp, o);
    }
    __shared__ float r_s[8], r_t[8];
    if (lane == 0) { r_s[w] = sp; r_t[w] = tp; }
    __syncthreads();
    if (tid == 0) {
        float S = 0.f, P = 0.f;
        #pragma unroll
        for (int k = 0; k < 8; k++) { S += r_s[k]; P += r_t[k]; }
        int nv = g_nvalid[b];
        int nu = g_nuni[b];
        float inu = 1.f / fmaxf((float)nu, 1.f);
        g_spatial[b]  = (nv > 1) ? S * inu : 0.f;
        g_temporal[b] = (nv > 2) ? P * inu : 0.f;
    }
}

// ======================= K3: IoU sweep (match / switch / fp) =======================
// grid: (NN/128, BB), 256 threads. Two threads per pred, each covers half of M.
__global__ __launch_bounds__(256) void k3_iou(
    const float4* __restrict__ pboxes,
    const float4* __restrict__ gboxes,
    const int*    __restrict__ pid,
    const int*    __restrict__ gid)
{
    const int b = blockIdx.y;
    const int tid = threadIdx.x;
    __shared__ float4 s_gb[MM];      // gt box
    __shared__ float2 s_meta[MM];    // (area, bits = gid | prflag<<8)
    __shared__ int    s_gtc[TT];
    __shared__ float  s_xmi[256];
    __shared__ int    s_xsw[256];

    const float4* gb4 = gboxes + b * MM;
    const int*   gidb = gid + b * MM;
    for (int j = tid; j < MM; j += 256) {
        float4 g = gb4[j];
        s_gb[j] = g;
        float a2 = fmaxf(g.z - g.x, 0.f) * fmaxf(g.w - g.y, 0.f);
        int gj = gidb[j];
        int bits = gj | ((g_pr_cnt[b][gj] > 0) ? 0x100 : 0);
        s_meta[j] = make_float2(a2, __int_as_float(bits));
    }
    if (tid < TT) s_gtc[tid] = g_gt_cnt[b][tid];
    __syncthreads();

    const int pi   = blockIdx.x * 128 + (tid & 127);
    const int half = tid >> 7;
    const int p    = pid[b * NN + pi];
    const bool valid = (p > 0);

    float mi = -1e30f;
    int swc = 0;
    if (valid) {
        float4 pbx = pboxes[b * NN + pi];
        const float px1 = pbx.x, py1 = pbx.y, px2 = pbx.z, py2 = pbx.w;
        const float a1 = fmaxf(px2 - px1, 0.f) * fmaxf(py2 - py1, 0.f);
        const int j0 = half * (MM / 2);
        const int j1 = j0 + (MM / 2);
        #pragma unroll 4
        for (int j = j0; j < j1; j++) {
            float4 g = s_gb[j];
            float2 mt = s_meta[j];
            float lx = fmaxf(px1, g.x), ly = fmaxf(py1, g.y);
            float rx = fminf(px2, g.z), ry = fminf(py2, g.w);
            float iw = fmaxf(rx - lx, 0.f), ih = fmaxf(ry - ly, 0.f);
            float inter = iw * ih;
            float uni = fmaxf(a1 + mt.x - inter, 1e-6f);
            float iou = __fdividef(inter, uni);
            int bits = __float_as_int(mt.y);
            int gidj = bits & 0xFF;
            bool same = (gidj == p);
            if (same) mi = fmaxf(mi, iou);
            if (iou > IOU_THR && !same && (bits & 0x100)) swc++;
        }
    }

    // combine the two halves of each pred
    s_xmi[tid] = mi;
    s_xsw[tid] = swc;
    __syncthreads();

    float matchv = 0.f, fpv = 0.f;
    int   swtot  = 0;
    if (tid < 128) {
        float m = fmaxf(s_xmi[tid], s_xmi[tid + 128]);
        swtot   = s_xsw[tid] + s_xsw[tid + 128];
        if (valid) {
            if (s_gtc[p] > 0) matchv = 1.f - m;
            else              fpv = 1.f;
        }
        // warp reduce (warps 0..3 full)
        #pragma unroll
        for (int o = 16; o > 0; o >>= 1) {
            matchv += __shfl_down_sync(0xffffffffu, matchv, o);
            fpv    += __shfl_down_sync(0xffffffffu, fpv, o);
            swtot  += __shfl_down_sync(0xffffffffu, swtot, o);
        }
        if ((tid & 31) == 0) {
            atomicAdd(&g_match[b], matchv);
            atomicAdd(&g_fp[b], fpv);
            atomicAdd(&g_sw[b], swtot);
        }
    }
}

// ======================= K4: finalize =======================
__global__ void k4_final(float* __restrict__ out)
{
    const int b = threadIdx.x;
    float lt = 0.f, ls = 0.f, lm = 0.f, nt = 0.f;
    if (b < BB) {
        float has = (g_nvalid[b] > 0) ? 1.f : 0.f;
        float tr = B_FN * g_fn[b] + g_match[b] + G_SW * (float)g_sw[b] + B_FP * g_fp[b];
        lt = tr * has;
        ls = g_spatial[b] * has;
        lm = g_temporal[b] * has;
        nt = (float)g_nuni[b] * has;
    }
    #pragma unroll
    for (int o = 16; o > 0; o >>= 1) {
        lt += __shfl_down_sync(0xffffffffu, lt, o);
        ls += __shfl_down_sync(0xffffffffu, ls, o);
        lm += __shfl_down_sync(0xffffffffu, lm, o);
        nt += __shfl_down_sync(0xffffffffu, nt, o);
    }
    if (b == 0) {
        float norm = (nt > 0.f) ? nt : 1.f;
        lt /= norm; ls /= norm; lm /= norm;
        out[0] = A_TRK * lt + A_SPA * ls + A_TMP * lm;
        out[1] = lt;
        out[2] = ls;
        out[3] = lm;
    }
}

// ======================= launch =======================
extern "C" void kernel_launch(void* const* d_in, const int* in_sizes, int n_in,
                              void* d_out, int out_size)
{
    const float4* pb  = (const float4*)d_in[0];  // pred_boxes [16,2048,4] f32
    const float4* gb  = (const float4*)d_in[1];  // gt_boxes   [16,1024,4] f32
    const int*    pid = (const int*)d_in[2];     // pred_track_ids [16,2048] i32
    const int*    gid = (const int*)d_in[3];     // gt_track_ids   [16,1024] i32
    float* out = (float*)d_out;

    k1_hist<<<BB, 256>>>(pb, pid, gid);
    k2_spat_temp<<<BB, 256>>>(pb, pid);
    k3_iou<<<dim3(NN / 128, BB), 256>>>(pb, gb, pid, gid);
    k4_final<<<1, 32>>>(out);
}